// round 9
// baseline (speedup 1.0000x reference)
#include <cuda_runtime.h>
#include <cuda_bf16.h>

#define TSEQ   2048
#define BATCH  4096
#define HDIM   32
#define STAGE  16
#define NSTAGE (TSEQ / STAGE)
#define NBMAX  3
#define NWARP  12
#define NB28BLOCKS 100   // blocks carrying 28 rows; remaining 48 carry 27

typedef unsigned long long ull;

// ---------- packed f32x2 helpers ----------
__device__ __forceinline__ ull pack2(float lo, float hi) {
    ull r;
    asm("mov.b64 %0, {%1, %2};" : "=l"(r) : "f"(lo), "f"(hi));
    return r;
}
__device__ __forceinline__ ull ffma2(ull a, ull b, ull c) {
    ull d;
    asm("fma.rn.f32x2 %0, %1, %2, %3;" : "=l"(d) : "l"(a), "l"(b), "l"(c));
    return d;
}
// non-hoistable shared load (keeps input weights out of the register file)
__device__ __forceinline__ ull lds64v(unsigned int saddr) {
    ull v;
    asm volatile("ld.shared.b64 %0, [%1];" : "=l"(v) : "r"(saddr));
    return v;
}
// duplicated store without pack MOVs
__device__ __forceinline__ void sts_dup(unsigned int saddr, float v) {
    asm volatile("st.shared.v2.f32 [%0], {%1, %1};" :: "r"(saddr), "f"(v));
}
// 4-byte async copy global -> shared (no destination register)
__device__ __forceinline__ void cp_async4(unsigned int saddr, const void* gaddr) {
    asm volatile("cp.async.ca.shared.global [%0], [%1], 4;"
                 :: "r"(saddr), "l"(gaddr));
}
__device__ __forceinline__ void cp_async_commit() {
    asm volatile("cp.async.commit_group;");
}
__device__ __forceinline__ void cp_async_wait0() {
    asm volatile("cp.async.wait_group 0;");
}

// ---------- single-MUFU tanh (sm_75+) ----------
__device__ __forceinline__ float tanhf_fast(float x) {
    float y;
    asm("tanh.approx.f32 %0, %1;" : "=f"(y) : "f"(x));
    return y;
}
// sigmoid(x) = 0.5*tanh(x/2) + 0.5 ; the /2 pre-folded into weights+bias.
__device__ __forceinline__ float sig_from_half(float xh) {
    return fmaf(0.5f, tanhf_fast(xh), 0.5f);
}

// One warp processes NB batch rows through all 2048 steps.
// Lane j owns h-index j. Gates packed (i,f),(g,o) into f32x2; sigmoid rows
// pre-scaled by 0.5. W_hh register-resident (128 regs); input weights+bias in
// smem (volatile LDS each step); x staged by cp.async (no staging registers).
template <int NB>
__device__ __forceinline__ void lstm_run(
    const float* __restrict__ x,
    const float* __restrict__ W_hh,
    float* __restrict__ out,
    ull (*hdup)[NBMAX][HDIM],          // [2][NBMAX][32] this warp's slice
    float (*xs)[NBMAX][STAGE][4],      // [2][NBMAX][16][4] this warp's x
    unsigned int wx_base,              // smem addr of wx[0][lane]
    int row0, int lane)
{
    constexpr int NE = NB * STAGE * 3;             // x elems per stage
    constexpr int NI = (NE + 31) / 32;             // cp.async iters

    // PyTorch gate rows for this lane: i, f, g, o
    const int r0 = lane;             // i  (sigmoid -> 0.5)
    const int r1 = HDIM + lane;      // f  (sigmoid -> 0.5)
    const int r2 = 2 * HDIM + lane;  // g  (tanh    -> 1.0)
    const int r3 = 3 * HDIM + lane;  // o  (sigmoid -> 0.5)

    // ---- recurrent weights into registers, gate-pair packed ----
    ull wif[HDIM], wgo[HDIM];
#pragma unroll
    for (int k = 0; k < HDIM; k++) {
        wif[k] = pack2(0.5f * W_hh[r0 * HDIM + k], 0.5f * W_hh[r1 * HDIM + k]);
        wgo[k] = pack2(       W_hh[r2 * HDIM + k], 0.5f * W_hh[r3 * HDIM + k]);
    }

    unsigned int hsts[2];
    hsts[0] = (unsigned int)__cvta_generic_to_shared(&hdup[0][0][lane]);
    hsts[1] = (unsigned int)__cvta_generic_to_shared(&hdup[1][0][lane]);
    unsigned int xs_s[2];
    xs_s[0] = (unsigned int)__cvta_generic_to_shared(&xs[0][0][0][0]);
    xs_s[1] = (unsigned int)__cvta_generic_to_shared(&xs[1][0][0][0]);

    float c[NB];
#pragma unroll
    for (int b = 0; b < NB; b++) {
        c[b] = 0.0f;
        hdup[0][b][lane] = 0ull;
    }

    // ---- stage 0 of x via cp.async ----
#pragma unroll
    for (int it = 0; it < NI; it++) {
        int idx = it * 32 + lane;
        if (idx < NE) {
            int b   = idx / (STAGE * 3);
            int rem = idx % (STAGE * 3);
            int t   = rem / 3, i = rem % 3;
            cp_async4(xs_s[0] + (unsigned)((b * STAGE + t) * 4 + i) * 4u,
                      x + (size_t)(row0 + b) * TSEQ * 3 + rem);
        }
    }
    cp_async_commit();
    cp_async_wait0();
    __syncwarp();

    int buf = 0;
#pragma unroll 1
    for (int s = 0; s < NSTAGE; s++) {
        // ---- prefetch next stage with cp.async into the other buffer ----
        if (s + 1 < NSTAGE) {
#pragma unroll
            for (int it = 0; it < NI; it++) {
                int idx = it * 32 + lane;
                if (idx < NE) {
                    int b   = idx / (STAGE * 3);
                    int rem = idx % (STAGE * 3);
                    int t   = rem / 3, i = rem % 3;
                    cp_async4(xs_s[buf ^ 1] + (unsigned)((b * STAGE + t) * 4 + i) * 4u,
                              x + (size_t)(row0 + b) * TSEQ * 3
                                + (size_t)(s + 1) * STAGE * 3 + rem);
                }
            }
            cp_async_commit();
        }

#pragma unroll 1
        for (int tt = 0; tt < STAGE; tt++) {
            const int rb = tt & 1;
            const int wb = rb ^ 1;

            // ---- input affine + bias (wx streamed from smem each step) ----
            ull aif[NB], ago[NB];
            {
                ull w0 = lds64v(wx_base + 0 * 256);
                ull w1 = lds64v(wx_base + 1 * 256);
                ull w2 = lds64v(wx_base + 2 * 256);
                ull g0 = lds64v(wx_base + 3 * 256);
                ull g1 = lds64v(wx_base + 4 * 256);
                ull g2 = lds64v(wx_base + 5 * 256);
                ull bi = lds64v(wx_base + 6 * 256);
                ull bg = lds64v(wx_base + 7 * 256);
#pragma unroll
                for (int b = 0; b < NB; b++) {
                    float xv0 = xs[buf][b][tt][0];
                    float xv1 = xs[buf][b][tt][1];
                    float xv2 = xs[buf][b][tt][2];
                    ull xp0 = pack2(xv0, xv0);
                    ull xp1 = pack2(xv1, xv1);
                    ull xp2 = pack2(xv2, xv2);
                    aif[b] = ffma2(xp0, w0, ffma2(xp1, w1, ffma2(xp2, w2, bi)));
                    ago[b] = ffma2(xp0, g0, ffma2(xp1, g1, ffma2(xp2, g2, bg)));
                }
            }

            // ---- recurrent matvec: kk-outer, rows inner; 2*NB chains ----
#pragma unroll
            for (int kk = 0; kk < HDIM; kk += 2) {
#pragma unroll
                for (int b = 0; b < NB; b++) {
                    ulonglong2 hd = *reinterpret_cast<const ulonglong2*>(&hdup[rb][b][kk]);
                    aif[b] = ffma2(wif[kk],     hd.x, aif[b]);
                    ago[b] = ffma2(wgo[kk],     hd.x, ago[b]);
                    aif[b] = ffma2(wif[kk + 1], hd.y, aif[b]);
                    ago[b] = ffma2(wgo[kk + 1], hd.y, ago[b]);
                }
            }

            // ---- activations + state update (i,f,o preacts pre-halved) ----
#pragma unroll
            for (int b = 0; b < NB; b++) {
                float2 vif = *reinterpret_cast<float2*>(&aif[b]);
                float2 vgo = *reinterpret_cast<float2*>(&ago[b]);
                float ig = sig_from_half(vif.x);
                float fg = sig_from_half(vif.y);
                float gg = tanhf_fast(vgo.x);
                float og = sig_from_half(vgo.y);
                c[b] = fmaf(fg, c[b], ig * gg);
                float hb = og * tanhf_fast(c[b]);
                sts_dup(hsts[wb] + (unsigned)b * (HDIM * 8), hb);
            }
            __syncwarp();   // h published before next step's reads
        }

        // ---- flip x buffer once prefetch has landed ----
        if (s + 1 < NSTAGE) {
            cp_async_wait0();
            __syncwarp();
            buf ^= 1;
        }
    }

    // Last step (tt=15) wrote parity buffer 0.
#pragma unroll
    for (int b = 0; b < NB; b++) {
        float2 hv = *reinterpret_cast<float2*>(&hdup[0][b][lane]);
        out[(size_t)(row0 + b) * HDIM + lane] = hv.x;
    }
}

// 12 warps/block; wid%4 -> SMSP, so SMSP k hosts wids k, k+4, k+8.
// 28-row blocks: NB = 3,3,3,3,2,2,2,2,2,2,2,2 -> every SMSP carries 3+2+2 = 7.
// 27-row blocks: NB = 3,3,3,2,2,2,2,2,2,2,2,2 -> SMSPs 7,7,7,6.
__device__ __constant__ int NB28[NWARP]  = {3,3,3,3,2,2,2,2,2,2,2,2};
__device__ __constant__ int OFF28[NWARP] = {0,3,6,9,12,14,16,18,20,22,24,26};
__device__ __constant__ int NB27[NWARP]  = {3,3,3,2,2,2,2,2,2,2,2,2};
__device__ __constant__ int OFF27[NWARP] = {0,3,6,9,11,13,15,17,19,21,23,25};

// 148 blocks x 384 threads: one block per SM, 3 warps per SMSP (reg cap 170).
__global__ void __launch_bounds__(384, 1)
lstm_kernel(const float* __restrict__ x,
            const float* __restrict__ W_ih,
            const float* __restrict__ W_hh,
            const float* __restrict__ b_ih,
            const float* __restrict__ b_hh,
            float* __restrict__ out)
{
    __shared__ __align__(16) ull   hd[NWARP][2][NBMAX][HDIM];
    __shared__ __align__(16) float xd[NWARP][2][NBMAX][STAGE][4];
    // input-weight rows + bias, shared by ALL warps (lane-indexed):
    // [0..2]=wxif, [3..5]=wxgo, [6]=bias_if, [7]=bias_go
    __shared__ __align__(16) ull   wx[8][32];

    const int tid  = threadIdx.x;
    const int wid  = tid >> 5;
    const int lane = tid & 31;
    const int bid  = blockIdx.x;

    // warp 0 fills the shared input-weight table
    if (wid == 0) {
        const int r0 = lane, r1 = HDIM + lane, r2 = 2 * HDIM + lane, r3 = 3 * HDIM + lane;
#pragma unroll
        for (int i = 0; i < 3; i++) {
            wx[i][lane]     = pack2(0.5f * W_ih[r0 * 3 + i], 0.5f * W_ih[r1 * 3 + i]);
            wx[3 + i][lane] = pack2(       W_ih[r2 * 3 + i], 0.5f * W_ih[r3 * 3 + i]);
        }
        wx[6][lane] = pack2(0.5f * (b_ih[r0] + b_hh[r0]), 0.5f * (b_ih[r1] + b_hh[r1]));
        wx[7][lane] = pack2(       (b_ih[r2] + b_hh[r2]), 0.5f * (b_ih[r3] + b_hh[r3]));
    }
    __syncthreads();

    const unsigned int wx_base =
        (unsigned int)__cvta_generic_to_shared(&wx[0][lane]);

    int row0, nb;
    if (bid < NB28BLOCKS) {
        row0 = bid * 28 + OFF28[wid];
        nb   = NB28[wid];
    } else {
        row0 = NB28BLOCKS * 28 + (bid - NB28BLOCKS) * 27 + OFF27[wid];
        nb   = NB27[wid];
    }

    if (nb == 3) {
        lstm_run<3>(x, W_hh, out, hd[wid], xd[wid], wx_base, row0, lane);
    } else {
        lstm_run<2>(x, W_hh, out, hd[wid], xd[wid], wx_base, row0, lane);
    }
}

extern "C" void kernel_launch(void* const* d_in, const int* in_sizes, int n_in,
                              void* d_out, int out_size)
{
    const float* x    = (const float*)d_in[0];
    const float* W_ih = (const float*)d_in[1];
    const float* W_hh = (const float*)d_in[2];
    const float* b_ih = (const float*)d_in[3];
    const float* b_hh = (const float*)d_in[4];
    float* out = (float*)d_out;

    lstm_kernel<<<148, 384>>>(x, W_ih, W_hh, b_ih, b_hh, out);
}

// round 10
// speedup vs baseline: 2.3571x; 2.3571x over previous
#include <cuda_runtime.h>
#include <cuda_bf16.h>

#define TSEQ   2048
#define BATCH  4096
#define HDIM   32
#define STAGE  16
#define NSTAGE (TSEQ / STAGE)
#define NBMAX  4
#define NB28BLOCKS 100   // blocks carrying 28 rows; remaining 48 carry 27

typedef unsigned long long ull;

// ---------- packed f32x2 helpers ----------
__device__ __forceinline__ ull pack2(float lo, float hi) {
    ull r;
    asm("mov.b64 %0, {%1, %2};" : "=l"(r) : "f"(lo), "f"(hi));
    return r;
}
__device__ __forceinline__ void unpack2(ull v, float& lo, float& hi) {
    asm("mov.b64 {%0, %1}, %2;" : "=f"(lo), "=f"(hi) : "l"(v));
}
__device__ __forceinline__ ull ffma2(ull a, ull b, ull c) {
    ull d;
    asm("fma.rn.f32x2 %0, %1, %2, %3;" : "=l"(d) : "l"(a), "l"(b), "l"(c));
    return d;
}
// 4-byte async copy global -> shared (no destination register)
__device__ __forceinline__ void cp_async4(unsigned int saddr, const void* gaddr) {
    asm volatile("cp.async.ca.shared.global [%0], [%1], 4;"
                 :: "r"(saddr), "l"(gaddr));
}
__device__ __forceinline__ void cp_async_commit() {
    asm volatile("cp.async.commit_group;");
}
__device__ __forceinline__ void cp_async_wait0() {
    asm volatile("cp.async.wait_group 0;");
}

// ---------- single-MUFU tanh (sm_75+) ----------
__device__ __forceinline__ float tanhf_fast(float x) {
    float y;
    asm("tanh.approx.f32 %0, %1;" : "=f"(y) : "f"(x));
    return y;
}
// sigmoid(x) = 0.5*tanh(x/2) + 0.5 ; the /2 pre-folded into weights+bias.
__device__ __forceinline__ float sig_from_half(float xh) {
    return fmaf(0.5f, tanhf_fast(xh), 0.5f);
}

// One warp processes NB batch rows through all 2048 steps.
// Lane j owns h-index j. Gates packed (i,f),(g,o) into f32x2; sigmoid rows
// pre-scaled by 0.5. W_hh fully register-resident (128 regs/lane).
// x staged pre-duplicated via cp.async (no staging registers in the hot loop).
template <int NB>
__device__ __forceinline__ void lstm_run(
    const float* __restrict__ x,
    const float* __restrict__ W_ih,
    const float* __restrict__ W_hh,
    const float* __restrict__ b_ih,
    const float* __restrict__ b_hh,
    float* __restrict__ out,
    ull (*hdup)[NBMAX][HDIM],        // [2][NBMAX][32] this warp's slice
    ull (*xdup)[NBMAX][STAGE][4],    // [2][NBMAX][STAGE][4] double-buffered
    int row0, int lane)
{
    constexpr int NE = NB * STAGE * 3;       // x elements per stage
    constexpr int NI = (NE + 31) / 32;       // cp.async iterations per lane

    // PyTorch gate rows for this lane: i, f, g, o
    const int r0 = lane;             // i  (sigmoid -> 0.5)
    const int r1 = HDIM + lane;      // f  (sigmoid -> 0.5)
    const int r2 = 2 * HDIM + lane;  // g  (tanh    -> 1.0)
    const int r3 = 3 * HDIM + lane;  // o  (sigmoid -> 0.5)

    // ---- recurrent weights into registers, gate-pair packed ----
    ull wif[HDIM], wgo[HDIM];
#pragma unroll
    for (int k = 0; k < HDIM; k++) {
        wif[k] = pack2(0.5f * W_hh[r0 * HDIM + k], 0.5f * W_hh[r1 * HDIM + k]);
        wgo[k] = pack2(       W_hh[r2 * HDIM + k], 0.5f * W_hh[r3 * HDIM + k]);
    }
    // ---- input weights + combined bias ----
    ull wxif[3], wxgo[3];
#pragma unroll
    for (int i = 0; i < 3; i++) {
        wxif[i] = pack2(0.5f * W_ih[r0 * 3 + i], 0.5f * W_ih[r1 * 3 + i]);
        wxgo[i] = pack2(       W_ih[r2 * 3 + i], 0.5f * W_ih[r3 * 3 + i]);
    }
    const ull bias_if = pack2(0.5f * (b_ih[r0] + b_hh[r0]),
                              0.5f * (b_ih[r1] + b_hh[r1]));
    const ull bias_go = pack2(       (b_ih[r2] + b_hh[r2]),
                              0.5f * (b_ih[r3] + b_hh[r3]));

    unsigned int xs_s[2];
    xs_s[0] = (unsigned int)__cvta_generic_to_shared(&xdup[0][0][0][0]);
    xs_s[1] = (unsigned int)__cvta_generic_to_shared(&xdup[1][0][0][0]);

    float c[NB];
#pragma unroll
    for (int b = 0; b < NB; b++) {
        c[b] = 0.0f;
        hdup[0][b][lane] = 0ull;
    }

    // ---- stage 0 of x via cp.async, written pre-duplicated (two 4B copies) ----
#pragma unroll
    for (int it = 0; it < NI; it++) {
        int idx = it * 32 + lane;
        if (idx < NE) {
            int b   = idx / (STAGE * 3);
            int rem = idx % (STAGE * 3);
            int t   = rem / 3, i = rem % 3;
            const float* g = x + (size_t)(row0 + b) * TSEQ * 3 + rem;
            unsigned int d = xs_s[0] + (unsigned)((b * STAGE + t) * 4 + i) * 8u;
            cp_async4(d,      g);
            cp_async4(d + 4u, g);
        }
    }
    cp_async_commit();
    cp_async_wait0();
    __syncwarp();

    int buf = 0;
#pragma unroll 1
    for (int s = 0; s < NSTAGE; s++) {
        // ---- prefetch next stage into the other buffer (fire and forget) ----
        if (s + 1 < NSTAGE) {
#pragma unroll
            for (int it = 0; it < NI; it++) {
                int idx = it * 32 + lane;
                if (idx < NE) {
                    int b   = idx / (STAGE * 3);
                    int rem = idx % (STAGE * 3);
                    int t   = rem / 3, i = rem % 3;
                    const float* g = x + (size_t)(row0 + b) * TSEQ * 3
                                       + (size_t)(s + 1) * STAGE * 3 + rem;
                    unsigned int d = xs_s[buf ^ 1] + (unsigned)((b * STAGE + t) * 4 + i) * 8u;
                    cp_async4(d,      g);
                    cp_async4(d + 4u, g);
                }
            }
            cp_async_commit();
        }

#pragma unroll 1
        for (int tt = 0; tt < STAGE; tt++) {
            const int rb = tt & 1;
            const int wb = rb ^ 1;

            // ---- input affine + bias (duplicated x straight from smem) ----
            ull aif[NB], ago[NB];
#pragma unroll
            for (int b = 0; b < NB; b++) {
                ulonglong2 x01 = *reinterpret_cast<const ulonglong2*>(&xdup[buf][b][tt][0]);
                ull x2 = xdup[buf][b][tt][2];
                aif[b] = ffma2(x01.x, wxif[0], ffma2(x01.y, wxif[1], ffma2(x2, wxif[2], bias_if)));
                ago[b] = ffma2(x01.x, wxgo[0], ffma2(x01.y, wxgo[1], ffma2(x2, wxgo[2], bias_go)));
            }

            // ---- recurrent matvec: kk-outer, rows inner; 2*NB chains ----
#pragma unroll
            for (int kk = 0; kk < HDIM; kk += 2) {
#pragma unroll
                for (int b = 0; b < NB; b++) {
                    ulonglong2 hd = *reinterpret_cast<const ulonglong2*>(&hdup[rb][b][kk]);
                    aif[b] = ffma2(wif[kk],     hd.x, aif[b]);
                    ago[b] = ffma2(wgo[kk],     hd.x, ago[b]);
                    aif[b] = ffma2(wif[kk + 1], hd.y, aif[b]);
                    ago[b] = ffma2(wgo[kk + 1], hd.y, ago[b]);
                }
            }

            // ---- activations + state update (i,f,o preacts pre-halved) ----
#pragma unroll
            for (int b = 0; b < NB; b++) {
                float ih, fh, gp, oh;
                unpack2(aif[b], ih, fh);
                unpack2(ago[b], gp, oh);
                float ig = sig_from_half(ih);
                float fg = sig_from_half(fh);
                float gg = tanhf_fast(gp);
                float og = sig_from_half(oh);
                c[b] = fmaf(fg, c[b], ig * gg);
                float hb = og * tanhf_fast(c[b]);
                hdup[wb][b][lane] = pack2(hb, hb);
            }
            __syncwarp();   // h published before next step's reads
        }

        // ---- flip x buffer once the prefetch has landed ----
        if (s + 1 < NSTAGE) {
            cp_async_wait0();
            __syncwarp();
            buf ^= 1;
        }
    }

    // Last step (tt=15) wrote parity buffer 0.
#pragma unroll
    for (int b = 0; b < NB; b++) {
        float lo, hi;
        unpack2(hdup[0][b][lane], lo, hi);
        out[(size_t)(row0 + b) * HDIM + lane] = lo;
    }
}

// Row distribution within a block. wid%4 -> SMSP, so wid i pairs with wid i+4.
// 28-row blocks: NB = 4,4,4,4,3,3,3,3  -> every SMSP pair carries 4+3 = 7 rows.
// 27-row blocks: NB = 4,4,4,3,3,3,3,3  -> pairs 7,7,7,6.
__device__ __constant__ int NB28[8]  = {4, 4, 4, 4, 3, 3, 3, 3};
__device__ __constant__ int OFF28[8] = {0, 4, 8, 12, 16, 19, 22, 25};
__device__ __constant__ int NB27[8]  = {4, 4, 4, 3, 3, 3, 3, 3};
__device__ __constant__ int OFF27[8] = {0, 4, 8, 12, 15, 18, 21, 24};

// 148 blocks x 256 threads: one block per SM, 2 warps per SMSP with
// controlled pairing; single wave, zero tail.
__global__ void __launch_bounds__(256, 1)
lstm_kernel(const float* __restrict__ x,
            const float* __restrict__ W_ih,
            const float* __restrict__ W_hh,
            const float* __restrict__ b_ih,
            const float* __restrict__ b_hh,
            float* __restrict__ out)
{
    __shared__ __align__(16) ull hd[8][2][NBMAX][HDIM];
    __shared__ __align__(16) ull xd[8][2][NBMAX][STAGE][4];

    const int wid  = threadIdx.x >> 5;
    const int lane = threadIdx.x & 31;
    const int bid  = blockIdx.x;

    int row0, nb;
    if (bid < NB28BLOCKS) {
        row0 = bid * 28 + OFF28[wid];
        nb   = NB28[wid];
    } else {
        row0 = NB28BLOCKS * 28 + (bid - NB28BLOCKS) * 27 + OFF27[wid];
        nb   = NB27[wid];
    }

    if (nb == 4) {
        lstm_run<4>(x, W_ih, W_hh, b_ih, b_hh, out, hd[wid], xd[wid], row0, lane);
    } else {
        lstm_run<3>(x, W_ih, W_hh, b_ih, b_hh, out, hd[wid], xd[wid], row0, lane);
    }
}

extern "C" void kernel_launch(void* const* d_in, const int* in_sizes, int n_in,
                              void* d_out, int out_size)
{
    const float* x    = (const float*)d_in[0];
    const float* W_ih = (const float*)d_in[1];
    const float* W_hh = (const float*)d_in[2];
    const float* b_ih = (const float*)d_in[3];
    const float* b_hh = (const float*)d_in[4];
    float* out = (float*)d_out;

    lstm_kernel<<<148, 256>>>(x, W_ih, W_hh, b_ih, b_hh, out);
}